// round 1
// baseline (speedup 1.0000x reference)
#include <cuda_runtime.h>

// ---------------------------------------------------------------------------
// TimeVarKP on GB300 — round 1: correct fp32 baseline with the z1==z_rec[:,7,:]
// algebraic simplification (second MHA eliminated; x_pred is a copy of the
// last segment of x_rec).
//
// Pipeline (all row-major fp32):
//   z    = X(4096x3072) @ enc_W(3072x1024) + enc_b                 [GEMM NN]
//   qkv  = z @ in_proj_W^T(1024x3072) + in_proj_b ; q *= 1/sqrt(128) [GEMM NT]
//   S_fh = Q_fh(512x128) @ K_fh^T                                   [GEMM NT, z=64]
//   P    = softmax_rows(S)
//   O_fh = P_fh @ V_fh(512x128)                                     [GEMM NN, z=64]
//   zrec = O(4096x1024) @ out_W^T + out_b                           [GEMM NT]
//   xrec = zrec @ dec_W(1024x3072) + dec_b  -> d_out[0 : 12582912]  [GEMM NN]
//   xpred[b,s,:,:] = xrec[b, 336:384, :]    -> d_out[12582912 : ]   [copy]
// ---------------------------------------------------------------------------

#define TILE_M 128
#define TILE_N 128
#define TILE_K 16

// Scratch (device globals -- no allocation allowed)
__device__ float g_z   [4096u * 1024u];   // 16 MB
__device__ float g_qkv [4096u * 3072u];   // 48 MB
__device__ float g_s   [64u * 512u * 512u]; // 64 MB
__device__ float g_o   [4096u * 1024u];   // 16 MB
__device__ float g_zrec[4096u * 1024u];   // 16 MB

// Generic tiled SGEMM. BT=false: B is (K,N) row-major. BT=true: B is (N,K)
// row-major (i.e. C = A @ B^T). Supports batched pointer offsets via
// blockIdx.z with a 2-level (outer/inner) stride decomposition:
//   zo = z / zDiv, zi = z % zDiv;  ptr += zo*Outer + zi*Inner.
// All of M,N divisible by 128, K by 16, all leading dims divisible by 4.
template <bool BT>
__global__ void __launch_bounds__(256)
sgemm_kernel(const float* __restrict__ Ag, const float* __restrict__ Bg,
             float* __restrict__ Cg, const float* __restrict__ bias,
             int M, int N, int K, int lda, int ldb, int ldc,
             long aOut, long aIn, long bOut, long bIn, long cOut, long cIn,
             int zDiv, int scaleLimit, float scale)
{
    __shared__ float As[TILE_K][TILE_M + 1];
    __shared__ float Bs[TILE_K][TILE_N + 1];

    const int z  = blockIdx.z;
    const int zo = z / zDiv;
    const int zi = z - zo * zDiv;
    const float* A = Ag + zo * aOut + zi * aIn;
    const float* B = Bg + zo * bOut + zi * bIn;
    float*       C = Cg + zo * cOut + zi * cIn;

    const int cRow = blockIdx.y * TILE_M;
    const int cCol = blockIdx.x * TILE_N;
    const int tid  = threadIdx.x;
    const int tRow = (tid >> 4) << 3;   // 0..120 step 8
    const int tCol = (tid & 15) << 3;   // 0..120 step 8

    float acc[8][8];
#pragma unroll
    for (int i = 0; i < 8; i++)
#pragma unroll
        for (int j = 0; j < 8; j++) acc[i][j] = 0.0f;

    for (int k0 = 0; k0 < K; k0 += TILE_K) {
        // --- load A tile (TILE_M x TILE_K), store transposed As[k][m] ---
#pragma unroll
        for (int i = 0; i < 2; i++) {
            int fid = tid + i * 256;          // float4 id in 128x16 tile
            int m   = fid >> 2;               // row (m)
            int kk  = (fid & 3) << 2;         // k offset
            float4 v = *(const float4*)(A + (long)(cRow + m) * lda + (k0 + kk));
            As[kk + 0][m] = v.x;
            As[kk + 1][m] = v.y;
            As[kk + 2][m] = v.z;
            As[kk + 3][m] = v.w;
        }
        // --- load B tile into Bs[k][n] ---
        if (!BT) {
#pragma unroll
            for (int i = 0; i < 2; i++) {
                int fid = tid + i * 256;      // float4 id in 16x128 tile (k,n)
                int kk  = fid >> 5;
                int n   = (fid & 31) << 2;
                float4 v = *(const float4*)(B + (long)(k0 + kk) * ldb + (cCol + n));
                Bs[kk][n + 0] = v.x;
                Bs[kk][n + 1] = v.y;
                Bs[kk][n + 2] = v.z;
                Bs[kk][n + 3] = v.w;
            }
        } else {
#pragma unroll
            for (int i = 0; i < 2; i++) {
                int fid = tid + i * 256;      // float4 id in 128x16 tile (n,k)
                int n   = fid >> 2;
                int kk  = (fid & 3) << 2;
                float4 v = *(const float4*)(B + (long)(cCol + n) * ldb + (k0 + kk));
                Bs[kk + 0][n] = v.x;
                Bs[kk + 1][n] = v.y;
                Bs[kk + 2][n] = v.z;
                Bs[kk + 3][n] = v.w;
            }
        }
        __syncthreads();

#pragma unroll
        for (int kk = 0; kk < TILE_K; kk++) {
            float ra[8], rb[8];
#pragma unroll
            for (int i = 0; i < 8; i++) ra[i] = As[kk][tRow + i];
#pragma unroll
            for (int j = 0; j < 8; j++) rb[j] = Bs[kk][tCol + j];
#pragma unroll
            for (int i = 0; i < 8; i++)
#pragma unroll
                for (int j = 0; j < 8; j++)
                    acc[i][j] = fmaf(ra[i], rb[j], acc[i][j]);
        }
        __syncthreads();
    }

    // --- epilogue: bias + optional column-range scaling (q scaling) ---
#pragma unroll
    for (int i = 0; i < 8; i++) {
        long row = (long)(cRow + tRow + i);
#pragma unroll
        for (int j = 0; j < 8; j++) {
            int col = cCol + tCol + j;
            float v = acc[i][j];
            if (bias) v += bias[col];
            if (col < scaleLimit) v *= scale;
            C[row * ldc + col] = v;
        }
    }
}

// Row softmax over rows of length 512. One block (256 threads) per row.
__global__ void __launch_bounds__(256) softmax512(float* __restrict__ S)
{
    long r = blockIdx.x;
    float* row = S + r * 512;
    int t    = threadIdx.x;
    int warp = t >> 5, lane = t & 31;

    float a = row[t];
    float b = row[t + 256];

    __shared__ float redM[8];
    __shared__ float redS[8];

    float m = fmaxf(a, b);
#pragma unroll
    for (int o = 16; o; o >>= 1) m = fmaxf(m, __shfl_xor_sync(0xffffffffu, m, o));
    if (lane == 0) redM[warp] = m;
    __syncthreads();
    float bm = redM[0];
#pragma unroll
    for (int i = 1; i < 8; i++) bm = fmaxf(bm, redM[i]);

    float e1 = __expf(a - bm);
    float e2 = __expf(b - bm);
    float s = e1 + e2;
#pragma unroll
    for (int o = 16; o; o >>= 1) s += __shfl_xor_sync(0xffffffffu, s, o);
    if (lane == 0) redS[warp] = s;
    __syncthreads();
    float bs = 0.0f;
#pragma unroll
    for (int i = 0; i < 8; i++) bs += redS[i];
    float inv = 1.0f / bs;

    row[t]       = e1 * inv;
    row[t + 256] = e2 * inv;
}

// x_pred[b, s, t, c] = x_rec[b, 336 + t, c]  (tile the last segment 4x)
// pred idx = b*12288 + s*3072 + j ;  src = rec[(b*8+7)*3072 + j]
__global__ void __launch_bounds__(256) pred_copy(const float* __restrict__ rec,
                                                 float* __restrict__ pred)
{
    long i   = (long)blockIdx.x * blockDim.x + threadIdx.x; // float4 index
    long idx = i * 4;                                       // < 6291456
    long b   = idx / 12288;
    long j   = idx % 3072;
    float4 v = *(const float4*)(rec + (b * 8 + 7) * 3072 + j);
    *(float4*)(pred + idx) = v;
}

extern "C" void kernel_launch(void* const* d_in, const int* in_sizes, int n_in,
                              void* d_out, int out_size)
{
    const float* x    = (const float*)d_in[0];
    const float* encW = (const float*)d_in[1];
    const float* encb = (const float*)d_in[2];
    const float* decW = (const float*)d_in[3];
    const float* decb = (const float*)d_in[4];
    const float* ipW  = (const float*)d_in[5];
    const float* ipb  = (const float*)d_in[6];
    const float* oW   = (const float*)d_in[7];
    const float* ob   = (const float*)d_in[8];

    float* rec  = (float*)d_out;            // 4096 x 3072 == (B,384,64)
    float* pred = rec + 12582912l;          // (B,192,64)

    float *zp, *qkvp, *sp, *op, *zrp;
    cudaGetSymbolAddress((void**)&zp,   g_z);
    cudaGetSymbolAddress((void**)&qkvp, g_qkv);
    cudaGetSymbolAddress((void**)&sp,   g_s);
    cudaGetSymbolAddress((void**)&op,   g_o);
    cudaGetSymbolAddress((void**)&zrp,  g_zrec);

    const dim3 blk(256);
    const float qscale = 0.08838834764831845f;   // 1/sqrt(128)

    // 1) enc: z = X @ enc_W + enc_b      (4096 x 1024 x 3072, NN)
    sgemm_kernel<false><<<dim3(8, 32, 1), blk>>>(
        x, encW, zp, encb,
        4096, 1024, 3072, 3072, 1024, 1024,
        0, 0, 0, 0, 0, 0, 1, 0, 1.0f);

    // 2) qkv = z @ in_proj_W^T + b ; scale q cols (<1024)  (4096 x 3072 x 1024, NT)
    sgemm_kernel<true><<<dim3(24, 32, 1), blk>>>(
        zp, ipW, qkvp, ipb,
        4096, 3072, 1024, 1024, 1024, 3072,
        0, 0, 0, 0, 0, 0, 1, 1024, qscale);

    // 3) scores: S_fh = Q_fh @ K_fh^T    (512 x 512 x 128, NT, 64 batches)
    //    z = f*8 + h ; Q base = qkv + f*3072 + h*128 ; K base = +1024
    sgemm_kernel<true><<<dim3(4, 4, 64), blk>>>(
        qkvp, qkvp + 1024, sp, nullptr,
        512, 512, 128, 24576, 24576, 512,
        3072, 128, 3072, 128, 2097152l, 262144l, 8, 0, 1.0f);

    // 4) softmax over rows (64*512 rows of 512)
    softmax512<<<32768, 256>>>(sp);

    // 5) O_fh = P_fh @ V_fh              (512 x 128 x 512, NN, 64 batches)
    sgemm_kernel<false><<<dim3(1, 4, 64), blk>>>(
        sp, qkvp + 2048, op, nullptr,
        512, 128, 512, 512, 24576, 8192,
        2097152l, 262144l, 3072, 128, 1024, 128, 8, 0, 1.0f);

    // 6) zrec = O @ out_W^T + out_b      (4096 x 1024 x 1024, NT)
    sgemm_kernel<true><<<dim3(8, 32, 1), blk>>>(
        op, oW, zrp, ob,
        4096, 1024, 1024, 1024, 1024, 1024,
        0, 0, 0, 0, 0, 0, 1, 0, 1.0f);

    // 7) x_rec = zrec @ dec_W + dec_b    (4096 x 3072 x 1024, NN) -> d_out
    sgemm_kernel<false><<<dim3(24, 32, 1), blk>>>(
        zrp, decW, rec, decb,
        4096, 3072, 1024, 1024, 3072, 3072,
        0, 0, 0, 0, 0, 0, 1, 0, 1.0f);

    // 8) x_pred = tile of last segment of x_rec
    pred_copy<<<6144, 256>>>(rec, pred);
}

// round 4
// speedup vs baseline: 2.4135x; 2.4135x over previous
#include <cuda_runtime.h>
#include <cuda_bf16.h>
#include <cstdint>

// ===========================================================================
// TimeVarKP — round 4 (round-3 resubmit after infra failure): all GEMMs via
// mma.sync (m16n8k16 bf16, fp32 accum) with bf16x3 splitting. tcgen05 is not
// available (harness compiles for plain sm_100 PTX target); ldmatrix +
// mma.sync + cp.async are.
//
//   z    = X @ encW' + b            (4096x1024x3072)   -> bf16 hi/lo
//   qkv  = z @ ipW^T + b            (4096x3072x1024)   -> fp32
//   S    = Q @ K^T  (64 batches of 512x512x128)        -> fp32
//   P    = softmax(S)                                  -> bf16 hi/lo
//   O    = P @ V    (64 batches of 512x128x512)        -> bf16 hi/lo (strided)
//   zrec = O @ oW^T + b             (4096x1024x1024)   -> bf16 hi/lo
//   xrec = zrec @ decW' + b         (4096x3072x1024)   -> d_out fp32
//   xpred = tile(xrec last segment)                    (z1 == z_rec[:,7,:])
// ===========================================================================

// ------------------------- device scratch (no allocs) ----------------------
__device__ __align__(256) __nv_bfloat16 g_xh [12582912], g_xl [12582912];
__device__ __align__(256) __nv_bfloat16 g_eWh[3145728],  g_eWl[3145728];
__device__ __align__(256) __nv_bfloat16 g_iWh[3145728],  g_iWl[3145728];
__device__ __align__(256) __nv_bfloat16 g_oWh[1048576],  g_oWl[1048576];
__device__ __align__(256) __nv_bfloat16 g_dWh[3145728],  g_dWl[3145728];
__device__ __align__(256) __nv_bfloat16 g_zh [4194304],  g_zl [4194304];
__device__ __align__(256) float         g_qkv[12582912];
__device__ __align__(256) __nv_bfloat16 g_Qh [4194304],  g_Ql [4194304];
__device__ __align__(256) __nv_bfloat16 g_Kh [4194304],  g_Kl [4194304];
__device__ __align__(256) __nv_bfloat16 g_Vth[4194304],  g_Vtl[4194304];
__device__ __align__(256) float         g_S  [16777216];
__device__ __align__(256) __nv_bfloat16 g_Ph [16777216], g_Pl [16777216];
__device__ __align__(256) __nv_bfloat16 g_Oh [4194304],  g_Ol [4194304];
__device__ __align__(256) __nv_bfloat16 g_zrh[4194304],  g_zrl[4194304];

// ------------------------------ helpers ------------------------------------
__device__ __forceinline__ uint32_t smem_u32(const void* p) {
    uint32_t a;
    asm("{ .reg .u64 t; cvta.to.shared.u64 t, %1; cvt.u32.u64 %0, t; }"
        : "=r"(a) : "l"(p));
    return a;
}
__device__ __forceinline__ void cpasync16(uint32_t dst, const void* src) {
    asm volatile("cp.async.cg.shared.global [%0], [%1], 16;"
                 :: "r"(dst), "l"(src));
}
#define CP_COMMIT() asm volatile("cp.async.commit_group;" ::: "memory")
#define CP_WAIT(n)  asm volatile("cp.async.wait_group %0;" :: "n"(n) : "memory")

__device__ __forceinline__ void ldsm4(uint32_t (&r)[4], uint32_t a) {
    asm volatile("ldmatrix.sync.aligned.m8n8.x4.shared.b16 {%0,%1,%2,%3}, [%4];"
        : "=r"(r[0]), "=r"(r[1]), "=r"(r[2]), "=r"(r[3]) : "r"(a));
}
__device__ __forceinline__ void mma16816(float (&d)[4], const uint32_t (&a)[4],
                                         uint32_t b0, uint32_t b1) {
    asm volatile(
        "mma.sync.aligned.m16n8k16.row.col.f32.bf16.bf16.f32 "
        "{%0,%1,%2,%3}, {%4,%5,%6,%7}, {%8,%9}, {%0,%1,%2,%3};"
        : "+f"(d[0]), "+f"(d[1]), "+f"(d[2]), "+f"(d[3])
        : "r"(a[0]), "r"(a[1]), "r"(a[2]), "r"(a[3]), "r"(b0), "r"(b1));
}

__device__ __forceinline__ void split1(float v, __nv_bfloat16& h, __nv_bfloat16& l) {
    h = __float2bfloat16(v);
    l = __float2bfloat16(v - __bfloat162float(h));
}

// --------------------------------- GEMM ------------------------------------
// smem tile: 128 rows x 32 k-cols bf16, padded row stride 40 elems (80 bytes).
// 80B stride makes every 8-row ldmatrix phase hit 8 distinct 16B segments.
#define ROWS_PAD   40
#define TILE_B     (128 * ROWS_PAD * 2)   // 10240 bytes
#define STAGE_B    (4 * TILE_B)           // Ah, Al, Bh, Bl = 40960
#define GEMM_SMEM  (2 * STAGE_B)          // 81920

__device__ __forceinline__ void load_stage(uint32_t base,
    const __nv_bfloat16* pAh, const __nv_bfloat16* pAl,
    const __nv_bfloat16* pBh, const __nv_bfloat16* pBl,
    int lda, int ldb, int k0, int tid)
{
#pragma unroll
    for (int i = 0; i < 2; i++) {
        int seg = tid + i * 256;          // 0..511
        int row = seg >> 2;
        int c16 = seg & 3;                // 16B chunk within 64B row
        uint32_t d = base + row * 80 + c16 * 16;
        long goA = (long)row * lda + k0 + c16 * 8;
        long goB = (long)row * ldb + k0 + c16 * 8;
        cpasync16(d,              pAh + goA);
        cpasync16(d + TILE_B,     pAl + goA);
        cpasync16(d + 2 * TILE_B, pBh + goB);
        cpasync16(d + 3 * TILE_B, pBl + goB);
    }
}

// C(M,N) = (Ah+Al)(M,K) @ (Bh+Bl)(N,K)^T  [3-product bf16 split, fp32 accum]
// Batched via blockIdx.z: zo=z/zDiv, zi=z%zDiv; ptr += zo*Out + zi*In.
__global__ void __launch_bounds__(256, 1)
gemm_mma3(const __nv_bfloat16* __restrict__ Ah, const __nv_bfloat16* __restrict__ Al,
          const __nv_bfloat16* __restrict__ Bh, const __nv_bfloat16* __restrict__ Bl,
          float* __restrict__ C, __nv_bfloat16* __restrict__ Chi,
          __nv_bfloat16* __restrict__ Clo, const float* __restrict__ bias,
          int K, int lda, int ldb, int ldc,
          long aOut, long aIn, long bOut, long bIn, long cOut, long cIn, int zDiv)
{
    extern __shared__ __align__(128) char smem[];
    const int tid  = threadIdx.x;
    const int lane = tid & 31;
    const int w    = tid >> 5;
    const int wm   = w & 3;    // 32-row slab within 128
    const int wn   = w >> 2;   // 64-col slab within 128
    uint32_t sb = smem_u32(smem);

    const int z  = blockIdx.z;
    const int zo = z / zDiv;
    const int zi = z - zo * zDiv;
    const __nv_bfloat16* pAh = Ah + zo * aOut + zi * aIn + (long)blockIdx.y * 128 * lda;
    const __nv_bfloat16* pAl = Al + zo * aOut + zi * aIn + (long)blockIdx.y * 128 * lda;
    const __nv_bfloat16* pBh = Bh + zo * bOut + zi * bIn + (long)blockIdx.x * 128 * ldb;
    const __nv_bfloat16* pBl = Bl + zo * bOut + zi * bIn + (long)blockIdx.x * 128 * ldb;

    float acc[2][8][4];
#pragma unroll
    for (int a = 0; a < 2; a++)
#pragma unroll
        for (int b = 0; b < 8; b++)
#pragma unroll
            for (int c = 0; c < 4; c++) acc[a][b][c] = 0.0f;

    const int nch = K >> 5;

    load_stage(sb, pAh, pAl, pBh, pBl, lda, ldb, 0, tid);
    CP_COMMIT();

    // per-lane ldmatrix address components (constant across chunks)
    const uint32_t arow  = (lane & 15);
    const uint32_t ahalf = (lane >> 4);          // k half (0/1)
    const uint32_t brow  = (lane & 7) + ((lane >> 4) << 3);
    const uint32_t bhalf = (lane >> 3) & 1;      // k half (0/1)

    for (int c = 0; c < nch; c++) {
        if (c + 1 < nch) {
            load_stage(sb + ((c + 1) & 1) * STAGE_B,
                       pAh, pAl, pBh, pBl, lda, ldb, (c + 1) << 5, tid);
            CP_COMMIT();
            CP_WAIT(1);
        } else {
            CP_WAIT(0);
        }
        __syncthreads();

        const uint32_t stage = sb + (c & 1) * STAGE_B;
#pragma unroll
        for (int ks = 0; ks < 2; ks++) {
            uint32_t aH[2][4], aL[2][4], bH[4][4], bL[4][4];
#pragma unroll
            for (int mt = 0; mt < 2; mt++) {
                uint32_t off = ((wm * 32 + mt * 16 + arow) * ROWS_PAD
                                + ks * 16 + ahalf * 8) * 2;
                ldsm4(aH[mt], stage + off);
                ldsm4(aL[mt], stage + TILE_B + off);
            }
#pragma unroll
            for (int p = 0; p < 4; p++) {
                uint32_t off = ((wn * 64 + p * 16 + brow) * ROWS_PAD
                                + ks * 16 + bhalf * 8) * 2;
                ldsm4(bH[p], stage + 2 * TILE_B + off);
                ldsm4(bL[p], stage + 3 * TILE_B + off);
            }
#pragma unroll
            for (int mt = 0; mt < 2; mt++)
#pragma unroll
                for (int p = 0; p < 4; p++) {
                    mma16816(acc[mt][2 * p],     aH[mt], bH[p][0], bH[p][1]);
                    mma16816(acc[mt][2 * p],     aH[mt], bL[p][0], bL[p][1]);
                    mma16816(acc[mt][2 * p],     aL[mt], bH[p][0], bH[p][1]);
                    mma16816(acc[mt][2 * p + 1], aH[mt], bH[p][2], bH[p][3]);
                    mma16816(acc[mt][2 * p + 1], aH[mt], bL[p][2], bL[p][3]);
                    mma16816(acc[mt][2 * p + 1], aL[mt], bH[p][2], bH[p][3]);
                }
        }
        __syncthreads();
    }

    // ---- epilogue: registers -> gmem (fp32 and/or bf16 hi/lo) --------------
    const long crow0 = (long)blockIdx.y * 128;
    float*         pC = C   ? C   + zo * cOut + zi * cIn + (long)blockIdx.x * 128 : nullptr;
    __nv_bfloat16* pH = Chi ? Chi + zo * cOut + zi * cIn + (long)blockIdx.x * 128 : nullptr;
    __nv_bfloat16* pL = Clo ? Clo + zo * cOut + zi * cIn + (long)blockIdx.x * 128 : nullptr;

#pragma unroll
    for (int mt = 0; mt < 2; mt++)
#pragma unroll
        for (int nt = 0; nt < 8; nt++) {
            int r0 = wm * 32 + mt * 16 + (lane >> 2);
            int cc = wn * 64 + nt * 8 + (lane & 3) * 2;
            float bv0 = 0.0f, bv1 = 0.0f;
            if (bias) {
                bv0 = bias[blockIdx.x * 128 + cc];
                bv1 = bias[blockIdx.x * 128 + cc + 1];
            }
#pragma unroll
            for (int h = 0; h < 2; h++) {
                long  r  = crow0 + r0 + h * 8;
                float v0 = acc[mt][nt][2 * h]     + bv0;
                float v1 = acc[mt][nt][2 * h + 1] + bv1;
                long  o  = r * (long)ldc + cc;
                if (pC) *(float2*)(pC + o) = make_float2(v0, v1);
                if (pH) {
                    __nv_bfloat16 h0, h1, l0, l1;
                    split1(v0, h0, l0);
                    split1(v1, h1, l1);
                    *(__nv_bfloat162*)(pH + o) = __nv_bfloat162(h0, h1);
                    *(__nv_bfloat162*)(pL + o) = __nv_bfloat162(l0, l1);
                }
            }
        }
}

// ---------------------------- auxiliary kernels -----------------------------
__global__ void __launch_bounds__(256)
split_plain(const float4* __restrict__ src, __nv_bfloat16* __restrict__ hi,
            __nv_bfloat16* __restrict__ lo, long n4)
{
    long i = (long)blockIdx.x * 256 + threadIdx.x;
    if (i >= n4) return;
    float4 v = src[i];
    __nv_bfloat16 h0, h1, h2, h3, l0, l1, l2, l3;
    split1(v.x, h0, l0); split1(v.y, h1, l1);
    split1(v.z, h2, l2); split1(v.w, h3, l3);
    ((__nv_bfloat162*)hi)[i * 2]     = __nv_bfloat162(h0, h1);
    ((__nv_bfloat162*)hi)[i * 2 + 1] = __nv_bfloat162(h2, h3);
    ((__nv_bfloat162*)lo)[i * 2]     = __nv_bfloat162(l0, l1);
    ((__nv_bfloat162*)lo)[i * 2 + 1] = __nv_bfloat162(l2, l3);
}

// src (R,C) row-major -> hi/lo (C,R)
__global__ void __launch_bounds__(256)
transpose_split(const float* __restrict__ src, int R, int C,
                __nv_bfloat16* __restrict__ hi, __nv_bfloat16* __restrict__ lo)
{
    __shared__ float t[32][33];
    int bx = blockIdx.x, by = blockIdx.y;
    int tx = threadIdx.x, ty = threadIdx.y;
#pragma unroll
    for (int i = 0; i < 4; i++) {
        int r = by * 32 + ty + i * 8, c = bx * 32 + tx;
        t[ty + i * 8][tx] = src[(long)r * C + c];
    }
    __syncthreads();
#pragma unroll
    for (int i = 0; i < 4; i++) {
        int oc  = bx * 32 + ty + i * 8;
        int orr = by * 32 + tx;
        float v = t[tx][ty + i * 8];
        long o = (long)oc * R + orr;
        __nv_bfloat16 h, l;
        split1(v, h, l);
        hi[o] = h; lo[o] = l;
    }
}

// qkv fp32 (4096x3072) -> Q,K bf16 pairs at [fh][b(512)][d(128)] (Q scaled)
__global__ void __launch_bounds__(128)
qkv_split(const float* __restrict__ qkv,
          __nv_bfloat16* __restrict__ Qh, __nv_bfloat16* __restrict__ Ql,
          __nv_bfloat16* __restrict__ Kh, __nv_bfloat16* __restrict__ Kl)
{
    int b = blockIdx.x, fh = blockIdx.y, f = fh >> 3, h = fh & 7, t = threadIdx.x;
    const float* base = qkv + (long)(b * 8 + f) * 3072 + h * 128;
    float q = base[t] * 0.08838834764831845f;
    float k = base[1024 + t];
    long o = ((long)fh * 512 + b) * 128 + t;
    __nv_bfloat16 hh, ll;
    split1(q, hh, ll); Qh[o] = hh; Ql[o] = ll;
    split1(k, hh, ll); Kh[o] = hh; Kl[o] = ll;
}

// V slice of qkv -> transposed bf16 pairs Vt[fh][d(128)][b(512)]
__global__ void __launch_bounds__(256)
vt_split(const float* __restrict__ qkv,
         __nv_bfloat16* __restrict__ Vth, __nv_bfloat16* __restrict__ Vtl)
{
    __shared__ float t[32][33];
    int dx = blockIdx.x, bx = blockIdx.y, fh = blockIdx.z;
    int f = fh >> 3, h = fh & 7;
    int tx = threadIdx.x, ty = threadIdx.y;
#pragma unroll
    for (int i = 0; i < 4; i++) {
        int b = bx * 32 + ty + i * 8, d = dx * 32 + tx;
        t[ty + i * 8][tx] = qkv[(long)(b * 8 + f) * 3072 + 2048 + h * 128 + d];
    }
    __syncthreads();
#pragma unroll
    for (int i = 0; i < 4; i++) {
        int d = dx * 32 + ty + i * 8, b = bx * 32 + tx;
        float v = t[tx][ty + i * 8];
        long o = ((long)fh * 128 + d) * 512 + b;
        __nv_bfloat16 h2, l2;
        split1(v, h2, l2);
        Vth[o] = h2; Vtl[o] = l2;
    }
}

// row softmax (512) -> bf16 hi/lo
__global__ void __launch_bounds__(256)
softmax_split(const float* __restrict__ S,
              __nv_bfloat16* __restrict__ Ph, __nv_bfloat16* __restrict__ Pl)
{
    long r = blockIdx.x;
    const float* row = S + r * 512;
    int t = threadIdx.x, warp = t >> 5, lane = t & 31;

    float a = row[t];
    float b = row[t + 256];

    __shared__ float redM[8], redS[8];
    float m = fmaxf(a, b);
#pragma unroll
    for (int o = 16; o; o >>= 1) m = fmaxf(m, __shfl_xor_sync(0xffffffffu, m, o));
    if (lane == 0) redM[warp] = m;
    __syncthreads();
    float bm = redM[0];
#pragma unroll
    for (int i = 1; i < 8; i++) bm = fmaxf(bm, redM[i]);

    float e1 = __expf(a - bm), e2 = __expf(b - bm);
    float s = e1 + e2;
#pragma unroll
    for (int o = 16; o; o >>= 1) s += __shfl_xor_sync(0xffffffffu, s, o);
    if (lane == 0) redS[warp] = s;
    __syncthreads();
    float bs = 0.0f;
#pragma unroll
    for (int i = 0; i < 8; i++) bs += redS[i];
    float inv = 1.0f / bs;

    __nv_bfloat16 h, l;
    split1(e1 * inv, h, l); Ph[r * 512 + t] = h;       Pl[r * 512 + t] = l;
    split1(e2 * inv, h, l); Ph[r * 512 + t + 256] = h; Pl[r * 512 + t + 256] = l;
}

__global__ void __launch_bounds__(256)
pred_copy(const float* __restrict__ rec, float* __restrict__ pred)
{
    long i   = (long)blockIdx.x * blockDim.x + threadIdx.x;
    long idx = i * 4;
    long b   = idx / 12288;
    long j   = idx % 3072;
    *(float4*)(pred + idx) = *(const float4*)(rec + (b * 8 + 7) * 3072 + j);
}

// --------------------------------- host ------------------------------------
extern "C" void kernel_launch(void* const* d_in, const int* in_sizes, int n_in,
                              void* d_out, int out_size)
{
    const float* x    = (const float*)d_in[0];
    const float* encW = (const float*)d_in[1];
    const float* encb = (const float*)d_in[2];
    const float* decW = (const float*)d_in[3];
    const float* decb = (const float*)d_in[4];
    const float* ipW  = (const float*)d_in[5];
    const float* ipb  = (const float*)d_in[6];
    const float* oW   = (const float*)d_in[7];
    const float* ob   = (const float*)d_in[8];

    float* rec  = (float*)d_out;
    float* pred = rec + 12582912l;

    cudaFuncSetAttribute(gemm_mma3, cudaFuncAttributeMaxDynamicSharedMemorySize, GEMM_SMEM);

#define SYM(T, p, s) T* p; cudaGetSymbolAddress((void**)&p, s)
    SYM(__nv_bfloat16, xh, g_xh);   SYM(__nv_bfloat16, xl, g_xl);
    SYM(__nv_bfloat16, eWh, g_eWh); SYM(__nv_bfloat16, eWl, g_eWl);
    SYM(__nv_bfloat16, iWh, g_iWh); SYM(__nv_bfloat16, iWl, g_iWl);
    SYM(__nv_bfloat16, oWh, g_oWh); SYM(__nv_bfloat16, oWl, g_oWl);
    SYM(__nv_bfloat16, dWh, g_dWh); SYM(__nv_bfloat16, dWl, g_dWl);
    SYM(__nv_bfloat16, zh, g_zh);   SYM(__nv_bfloat16, zl, g_zl);
    SYM(float, qkvf, g_qkv);
    SYM(__nv_bfloat16, Qh, g_Qh);   SYM(__nv_bfloat16, Ql, g_Ql);
    SYM(__nv_bfloat16, Kh, g_Kh);   SYM(__nv_bfloat16, Kl, g_Kl);
    SYM(__nv_bfloat16, Vth, g_Vth); SYM(__nv_bfloat16, Vtl, g_Vtl);
    SYM(float, Sf, g_S);
    SYM(__nv_bfloat16, Ph, g_Ph);   SYM(__nv_bfloat16, Pl, g_Pl);
    SYM(__nv_bfloat16, Oh, g_Oh);   SYM(__nv_bfloat16, Ol, g_Ol);
    SYM(__nv_bfloat16, zrh, g_zrh); SYM(__nv_bfloat16, zrl, g_zrl);
#undef SYM

    // input / weight conversions
    split_plain<<<12288, 256>>>((const float4*)x, xh, xl, 3145728);
    transpose_split<<<dim3(32, 96), dim3(32, 8)>>>(encW, 3072, 1024, eWh, eWl);
    split_plain<<<3072, 256>>>((const float4*)ipW, iWh, iWl, 786432);
    split_plain<<<1024, 256>>>((const float4*)oW, oWh, oWl, 262144);
    transpose_split<<<dim3(96, 32), dim3(32, 8)>>>(decW, 1024, 3072, dWh, dWl);

    // enc: z = X @ encW  (bf16 out)
    gemm_mma3<<<dim3(8, 32, 1), 256, GEMM_SMEM>>>(
        xh, xl, eWh, eWl, nullptr, zh, zl, encb,
        3072, 3072, 3072, 1024, 0, 0, 0, 0, 0, 0, 1);

    // qkv = z @ ipW^T + b (fp32 out)
    gemm_mma3<<<dim3(24, 32, 1), 256, GEMM_SMEM>>>(
        zh, zl, iWh, iWl, qkvf, nullptr, nullptr, ipb,
        1024, 1024, 1024, 3072, 0, 0, 0, 0, 0, 0, 1);

    qkv_split<<<dim3(512, 64), 128>>>(qkvf, Qh, Ql, Kh, Kl);
    vt_split<<<dim3(4, 16, 64), dim3(32, 8)>>>(qkvf, Vth, Vtl);

    // scores: S = Q @ K^T (64 batches of 512x512x128)
    gemm_mma3<<<dim3(4, 4, 64), 256, GEMM_SMEM>>>(
        Qh, Ql, Kh, Kl, Sf, nullptr, nullptr, nullptr,
        128, 128, 128, 512, 65536, 0, 65536, 0, 262144, 0, 1);

    softmax_split<<<32768, 256>>>(Sf, Ph, Pl);

    // O = P @ V (64 batches of 512x128x512, strided bf16 out into 4096x1024)
    gemm_mma3<<<dim3(1, 4, 64), 256, GEMM_SMEM>>>(
        Ph, Pl, Vth, Vtl, nullptr, Oh, Ol, nullptr,
        512, 512, 512, 8192, 2097152, 262144, 524288, 65536, 1024, 128, 8);

    // zrec = O @ oW^T + b (bf16 out)
    gemm_mma3<<<dim3(8, 32, 1), 256, GEMM_SMEM>>>(
        Oh, Ol, oWh, oWl, nullptr, zrh, zrl, ob,
        1024, 1024, 1024, 1024, 0, 0, 0, 0, 0, 0, 1);

    // xrec = zrec @ decW + b (fp32 -> d_out)
    gemm_mma3<<<dim3(24, 32, 1), 256, GEMM_SMEM>>>(
        zrh, zrl, dWh, dWl, rec, nullptr, nullptr, decb,
        1024, 1024, 1024, 3072, 0, 0, 0, 0, 0, 0, 1);

    pred_copy<<<6144, 256>>>(rec, pred);
}

// round 7
// speedup vs baseline: 2.4561x; 1.0177x over previous
#include <cuda_runtime.h>
#include <cuda_bf16.h>
#include <cstdint>

// ===========================================================================
// TimeVarKP — round 7: bf16x3 mma.sync GEMMs, 3-stage cp.async pipeline
// (1 barrier per K-chunk, 120KB smem — hedged down from the 4-stage/160KB
// variant that coincided with repeated container failures).
//
//   z    = X @ encW' + b            (4096x1024x3072)   -> bf16 hi/lo
//   qkv  = z @ ipW^T + b            (4096x3072x1024)   -> fp32
//   S    = Q @ K^T  (64 batches of 512x512x128)        -> fp32
//   P    = softmax(S)                                  -> bf16 hi/lo
//   O    = P @ V    (64 batches of 512x128x512)        -> bf16 hi/lo (strided)
//   zrec = O @ oW^T + b             (4096x1024x1024)   -> bf16 hi/lo
//   xrec = zrec @ decW' + b         (4096x3072x1024)   -> d_out fp32
//   xpred = tile(xrec last segment)                    (z1 == z_rec[:,7,:])
// ===========================================================================

// ------------------------- device scratch (no allocs) ----------------------
__device__ __align__(256) __nv_bfloat16 g_xh [12582912], g_xl [12582912];
__device__ __align__(256) __nv_bfloat16 g_eWh[3145728],  g_eWl[3145728];
__device__ __align__(256) __nv_bfloat16 g_iWh[3145728],  g_iWl[3145728];
__device__ __align__(256) __nv_bfloat16 g_oWh[1048576],  g_oWl[1048576];
__device__ __align__(256) __nv_bfloat16 g_dWh[3145728],  g_dWl[3145728];
__device__ __align__(256) __nv_bfloat16 g_zh [4194304],  g_zl [4194304];
__device__ __align__(256) float         g_qkv[12582912];
__device__ __align__(256) __nv_bfloat16 g_Qh [4194304],  g_Ql [4194304];
__device__ __align__(256) __nv_bfloat16 g_Kh [4194304],  g_Kl [4194304];
__device__ __align__(256) __nv_bfloat16 g_Vth[4194304],  g_Vtl[4194304];
__device__ __align__(256) float         g_S  [16777216];
__device__ __align__(256) __nv_bfloat16 g_Ph [16777216], g_Pl [16777216];
__device__ __align__(256) __nv_bfloat16 g_Oh [4194304],  g_Ol [4194304];
__device__ __align__(256) __nv_bfloat16 g_zrh[4194304],  g_zrl[4194304];

// ------------------------------ helpers ------------------------------------
__device__ __forceinline__ uint32_t smem_u32(const void* p) {
    uint32_t a;
    asm("{ .reg .u64 t; cvta.to.shared.u64 t, %1; cvt.u32.u64 %0, t; }"
        : "=r"(a) : "l"(p));
    return a;
}
__device__ __forceinline__ void cpasync16(uint32_t dst, const void* src) {
    asm volatile("cp.async.cg.shared.global [%0], [%1], 16;"
                 :: "r"(dst), "l"(src));
}
#define CP_COMMIT() asm volatile("cp.async.commit_group;" ::: "memory")
#define CP_WAIT(n)  asm volatile("cp.async.wait_group %0;" :: "n"(n) : "memory")

__device__ __forceinline__ void ldsm4(uint32_t (&r)[4], uint32_t a) {
    asm volatile("ldmatrix.sync.aligned.m8n8.x4.shared.b16 {%0,%1,%2,%3}, [%4];"
        : "=r"(r[0]), "=r"(r[1]), "=r"(r[2]), "=r"(r[3]) : "r"(a));
}
__device__ __forceinline__ void mma16816(float (&d)[4], const uint32_t (&a)[4],
                                         uint32_t b0, uint32_t b1) {
    asm volatile(
        "mma.sync.aligned.m16n8k16.row.col.f32.bf16.bf16.f32 "
        "{%0,%1,%2,%3}, {%4,%5,%6,%7}, {%8,%9}, {%0,%1,%2,%3};"
        : "+f"(d[0]), "+f"(d[1]), "+f"(d[2]), "+f"(d[3])
        : "r"(a[0]), "r"(a[1]), "r"(a[2]), "r"(a[3]), "r"(b0), "r"(b1));
}

__device__ __forceinline__ void split1(float v, __nv_bfloat16& h, __nv_bfloat16& l) {
    h = __float2bfloat16(v);
    l = __float2bfloat16(v - __bfloat162float(h));
}

// --------------------------------- GEMM ------------------------------------
// smem tile: 128 rows x 32 k-cols bf16, padded row stride 40 elems (80 bytes).
// 80B stride makes every 8-row ldmatrix phase hit 8 distinct 16B segments.
#define ROWS_PAD   40
#define TILE_B     (128 * ROWS_PAD * 2)   // 10240 bytes
#define STAGE_B    (4 * TILE_B)           // Ah, Al, Bh, Bl = 40960
#define NSTAGE     3
#define GEMM_SMEM  (NSTAGE * STAGE_B)     // 122880

__device__ __forceinline__ void load_stage(uint32_t base,
    const __nv_bfloat16* pAh, const __nv_bfloat16* pAl,
    const __nv_bfloat16* pBh, const __nv_bfloat16* pBl,
    int lda, int ldb, int k0, int tid)
{
#pragma unroll
    for (int i = 0; i < 2; i++) {
        int seg = tid + i * 256;          // 0..511
        int row = seg >> 2;
        int c16 = seg & 3;                // 16B chunk within 64B row
        uint32_t d = base + row * 80 + c16 * 16;
        long goA = (long)row * lda + k0 + c16 * 8;
        long goB = (long)row * ldb + k0 + c16 * 8;
        cpasync16(d,              pAh + goA);
        cpasync16(d + TILE_B,     pAl + goA);
        cpasync16(d + 2 * TILE_B, pBh + goB);
        cpasync16(d + 3 * TILE_B, pBl + goB);
    }
}

// C(M,N) = (Ah+Al)(M,K) @ (Bh+Bl)(N,K)^T  [3-product bf16 split, fp32 accum]
// Batched via blockIdx.z: zo=z/zDiv, zi=z%zDiv; ptr += zo*Out + zi*In.
__global__ void __launch_bounds__(256, 1)
gemm_mma3(const __nv_bfloat16* __restrict__ Ah, const __nv_bfloat16* __restrict__ Al,
          const __nv_bfloat16* __restrict__ Bh, const __nv_bfloat16* __restrict__ Bl,
          float* __restrict__ C, __nv_bfloat16* __restrict__ Chi,
          __nv_bfloat16* __restrict__ Clo, const float* __restrict__ bias,
          int K, int lda, int ldb, int ldc,
          long aOut, long aIn, long bOut, long bIn, long cOut, long cIn, int zDiv)
{
    extern __shared__ __align__(128) char smem[];
    const int tid  = threadIdx.x;
    const int lane = tid & 31;
    const int w    = tid >> 5;
    const int wm   = w & 3;    // 32-row slab within 128
    const int wn   = w >> 2;   // 64-col slab within 128
    uint32_t sb = smem_u32(smem);

    const int z  = blockIdx.z;
    const int zo = z / zDiv;
    const int zi = z - zo * zDiv;
    const __nv_bfloat16* pAh = Ah + zo * aOut + zi * aIn + (long)blockIdx.y * 128 * lda;
    const __nv_bfloat16* pAl = Al + zo * aOut + zi * aIn + (long)blockIdx.y * 128 * lda;
    const __nv_bfloat16* pBh = Bh + zo * bOut + zi * bIn + (long)blockIdx.x * 128 * ldb;
    const __nv_bfloat16* pBl = Bl + zo * bOut + zi * bIn + (long)blockIdx.x * 128 * ldb;

    float acc[2][8][4];
#pragma unroll
    for (int a = 0; a < 2; a++)
#pragma unroll
        for (int b = 0; b < 8; b++)
#pragma unroll
            for (int c = 0; c < 4; c++) acc[a][b][c] = 0.0f;

    const int nch = K >> 5;

    // ---- prologue: fill NSTAGE-1 stages, one commit group per stage -------
#pragma unroll
    for (int s = 0; s < NSTAGE - 1; s++) {
        if (s < nch)
            load_stage(sb + s * STAGE_B, pAh, pAl, pBh, pBl, lda, ldb, s << 5, tid);
        CP_COMMIT();
    }

    // per-lane ldmatrix address components (constant across chunks)
    const uint32_t arow  = (lane & 15);
    const uint32_t ahalf = (lane >> 4);          // k half (0/1)
    const uint32_t brow  = (lane & 7) + ((lane >> 4) << 3);
    const uint32_t bhalf = (lane >> 3) & 1;      // k half (0/1)

    int stageIdx = 0, loadIdx = NSTAGE - 1;
    for (int c = 0; c < nch; c++) {
        CP_WAIT(NSTAGE - 2);                     // chunk c resident
        __syncthreads();                         // all warps done with chunk c-1

        const int nc = c + NSTAGE - 1;           // next chunk to fetch
        if (nc < nch) {                          // writes stage (c-1)%NSTAGE
            if (loadIdx >= NSTAGE) loadIdx = 0;
            load_stage(sb + loadIdx * STAGE_B,
                       pAh, pAl, pBh, pBl, lda, ldb, nc << 5, tid);
            loadIdx++;
        }
        CP_COMMIT();                             // exactly one group per iter

        const uint32_t stage = sb + stageIdx * STAGE_B;
        if (++stageIdx == NSTAGE) stageIdx = 0;
#pragma unroll
        for (int ks = 0; ks < 2; ks++) {
            uint32_t aH[2][4], aL[2][4], bH[4][4], bL[4][4];
#pragma unroll
            for (int mt = 0; mt < 2; mt++) {
                uint32_t off = ((wm * 32 + mt * 16 + arow) * ROWS_PAD
                                + ks * 16 + ahalf * 8) * 2;
                ldsm4(aH[mt], stage + off);
                ldsm4(aL[mt], stage + TILE_B + off);
            }
#pragma unroll
            for (int p = 0; p < 4; p++) {
                uint32_t off = ((wn * 64 + p * 16 + brow) * ROWS_PAD
                                + ks * 16 + bhalf * 8) * 2;
                ldsm4(bH[p], stage + 2 * TILE_B + off);
                ldsm4(bL[p], stage + 3 * TILE_B + off);
            }
#pragma unroll
            for (int mt = 0; mt < 2; mt++)
#pragma unroll
                for (int p = 0; p < 4; p++) {
                    mma16816(acc[mt][2 * p],     aH[mt], bH[p][0], bH[p][1]);
                    mma16816(acc[mt][2 * p],     aH[mt], bL[p][0], bL[p][1]);
                    mma16816(acc[mt][2 * p],     aL[mt], bH[p][0], bH[p][1]);
                    mma16816(acc[mt][2 * p + 1], aH[mt], bH[p][2], bH[p][3]);
                    mma16816(acc[mt][2 * p + 1], aH[mt], bL[p][2], bL[p][3]);
                    mma16816(acc[mt][2 * p + 1], aL[mt], bH[p][2], bH[p][3]);
                }
        }
    }

    // ---- epilogue: registers -> gmem (fp32 and/or bf16 hi/lo) --------------
    const long crow0 = (long)blockIdx.y * 128;
    float*         pC = C   ? C   + zo * cOut + zi * cIn + (long)blockIdx.x * 128 : nullptr;
    __nv_bfloat16* pH = Chi ? Chi + zo * cOut + zi * cIn + (long)blockIdx.x * 128 : nullptr;
    __nv_bfloat16* pL = Clo ? Clo + zo * cOut + zi * cIn + (long)blockIdx.x * 128 : nullptr;

#pragma unroll
    for (int mt = 0; mt < 2; mt++)
#pragma unroll
        for (int nt = 0; nt < 8; nt++) {
            int r0 = wm * 32 + mt * 16 + (lane >> 2);
            int cc = wn * 64 + nt * 8 + (lane & 3) * 2;
            float bv0 = 0.0f, bv1 = 0.0f;
            if (bias) {
                bv0 = bias[blockIdx.x * 128 + cc];
                bv1 = bias[blockIdx.x * 128 + cc + 1];
            }
#pragma unroll
            for (int h = 0; h < 2; h++) {
                long  r  = crow0 + r0 + h * 8;
                float v0 = acc[mt][nt][2 * h]     + bv0;
                float v1 = acc[mt][nt][2 * h + 1] + bv1;
                long  o  = r * (long)ldc + cc;
                if (pC) *(float2*)(pC + o) = make_float2(v0, v1);
                if (pH) {
                    __nv_bfloat16 h0, h1, l0, l1;
                    split1(v0, h0, l0);
                    split1(v1, h1, l1);
                    *(__nv_bfloat162*)(pH + o) = __nv_bfloat162(h0, h1);
                    *(__nv_bfloat162*)(pL + o) = __nv_bfloat162(l0, l1);
                }
            }
        }
}

// ---------------------------- auxiliary kernels -----------------------------
__global__ void __launch_bounds__(256)
split_plain(const float4* __restrict__ src, __nv_bfloat16* __restrict__ hi,
            __nv_bfloat16* __restrict__ lo, long n4)
{
    long i = (long)blockIdx.x * 256 + threadIdx.x;
    if (i >= n4) return;
    float4 v = src[i];
    __nv_bfloat16 h0, h1, h2, h3, l0, l1, l2, l3;
    split1(v.x, h0, l0); split1(v.y, h1, l1);
    split1(v.z, h2, l2); split1(v.w, h3, l3);
    ((__nv_bfloat162*)hi)[i * 2]     = __nv_bfloat162(h0, h1);
    ((__nv_bfloat162*)hi)[i * 2 + 1] = __nv_bfloat162(h2, h3);
    ((__nv_bfloat162*)lo)[i * 2]     = __nv_bfloat162(l0, l1);
    ((__nv_bfloat162*)lo)[i * 2 + 1] = __nv_bfloat162(l2, l3);
}

// src (R,C) row-major -> hi/lo (C,R)
__global__ void __launch_bounds__(256)
transpose_split(const float* __restrict__ src, int R, int C,
                __nv_bfloat16* __restrict__ hi, __nv_bfloat16* __restrict__ lo)
{
    __shared__ float t[32][33];
    int bx = blockIdx.x, by = blockIdx.y;
    int tx = threadIdx.x, ty = threadIdx.y;
#pragma unroll
    for (int i = 0; i < 4; i++) {
        int r = by * 32 + ty + i * 8, c = bx * 32 + tx;
        t[ty + i * 8][tx] = src[(long)r * C + c];
    }
    __syncthreads();
#pragma unroll
    for (int i = 0; i < 4; i++) {
        int oc  = bx * 32 + ty + i * 8;
        int orr = by * 32 + tx;
        float v = t[tx][ty + i * 8];
        long o = (long)oc * R + orr;
        __nv_bfloat16 h, l;
        split1(v, h, l);
        hi[o] = h; lo[o] = l;
    }
}

// qkv fp32 (4096x3072) -> Q,K bf16 pairs at [fh][b(512)][d(128)] (Q scaled)
__global__ void __launch_bounds__(128)
qkv_split(const float* __restrict__ qkv,
          __nv_bfloat16* __restrict__ Qh, __nv_bfloat16* __restrict__ Ql,
          __nv_bfloat16* __restrict__ Kh, __nv_bfloat16* __restrict__ Kl)
{
    int b = blockIdx.x, fh = blockIdx.y, f = fh >> 3, h = fh & 7, t = threadIdx.x;
    const float* base = qkv + (long)(b * 8 + f) * 3072 + h * 128;
    float q = base[t] * 0.08838834764831845f;
    float k = base[1024 + t];
    long o = ((long)fh * 512 + b) * 128 + t;
    __nv_bfloat16 hh, ll;
    split1(q, hh, ll); Qh[o] = hh; Ql[o] = ll;
    split1(k, hh, ll); Kh[o] = hh; Kl[o] = ll;
}

// V slice of qkv -> transposed bf16 pairs Vt[fh][d(128)][b(512)]
__global__ void __launch_bounds__(256)
vt_split(const float* __restrict__ qkv,
         __nv_bfloat16* __restrict__ Vth, __nv_bfloat16* __restrict__ Vtl)
{
    __shared__ float t[32][33];
    int dx = blockIdx.x, bx = blockIdx.y, fh = blockIdx.z;
    int f = fh >> 3, h = fh & 7;
    int tx = threadIdx.x, ty = threadIdx.y;
#pragma unroll
    for (int i = 0; i < 4; i++) {
        int b = bx * 32 + ty + i * 8, d = dx * 32 + tx;
        t[ty + i * 8][tx] = qkv[(long)(b * 8 + f) * 3072 + 2048 + h * 128 + d];
    }
    __syncthreads();
#pragma unroll
    for (int i = 0; i < 4; i++) {
        int d = dx * 32 + ty + i * 8, b = bx * 32 + tx;
        float v = t[tx][ty + i * 8];
        long o = ((long)fh * 128 + d) * 512 + b;
        __nv_bfloat16 h2, l2;
        split1(v, h2, l2);
        Vth[o] = h2; Vtl[o] = l2;
    }
}

// row softmax (512) -> bf16 hi/lo
__global__ void __launch_bounds__(256)
softmax_split(const float* __restrict__ S,
              __nv_bfloat16* __restrict__ Ph, __nv_bfloat16* __restrict__ Pl)
{
    long r = blockIdx.x;
    const float* row = S + r * 512;
    int t = threadIdx.x, warp = t >> 5, lane = t & 31;

    float a = row[t];
    float b = row[t + 256];

    __shared__ float redM[8], redS[8];
    float m = fmaxf(a, b);
#pragma unroll
    for (int o = 16; o; o >>= 1) m = fmaxf(m, __shfl_xor_sync(0xffffffffu, m, o));
    if (lane == 0) redM[warp] = m;
    __syncthreads();
    float bm = redM[0];
#pragma unroll
    for (int i = 1; i < 8; i++) bm = fmaxf(bm, redM[i]);

    float e1 = __expf(a - bm), e2 = __expf(b - bm);
    float s = e1 + e2;
#pragma unroll
    for (int o = 16; o; o >>= 1) s += __shfl_xor_sync(0xffffffffu, s, o);
    if (lane == 0) redS[warp] = s;
    __syncthreads();
    float bs = 0.0f;
#pragma unroll
    for (int i = 0; i < 8; i++) bs += redS[i];
    float inv = 1.0f / bs;

    __nv_bfloat16 h, l;
    split1(e1 * inv, h, l); Ph[r * 512 + t] = h;       Pl[r * 512 + t] = l;
    split1(e2 * inv, h, l); Ph[r * 512 + t + 256] = h; Pl[r * 512 + t + 256] = l;
}

__global__ void __launch_bounds__(256)
pred_copy(const float* __restrict__ rec, float* __restrict__ pred)
{
    long i   = (long)blockIdx.x * blockDim.x + threadIdx.x;
    long idx = i * 4;
    long b   = idx / 12288;
    long j   = idx % 3072;
    *(float4*)(pred + idx) = *(const float4*)(rec + (b * 8 + 7) * 3072 + j);
}

// --------------------------------- host ------------------------------------
extern "C" void kernel_launch(void* const* d_in, const int* in_sizes, int n_in,
                              void* d_out, int out_size)
{
    const float* x    = (const float*)d_in[0];
    const float* encW = (const float*)d_in[1];
    const float* encb = (const float*)d_in[2];
    const float* decW = (const float*)d_in[3];
    const float* decb = (const float*)d_in[4];
    const float* ipW  = (const float*)d_in[5];
    const float* ipb  = (const float*)d_in[6];
    const float* oW   = (const float*)d_in[7];
    const float* ob   = (const float*)d_in[8];

    float* rec  = (float*)d_out;
    float* pred = rec + 12582912l;

    cudaFuncSetAttribute(gemm_mma3, cudaFuncAttributeMaxDynamicSharedMemorySize, GEMM_SMEM);

#define SYM(T, p, s) T* p; cudaGetSymbolAddress((void**)&p, s)
    SYM(__nv_bfloat16, xh, g_xh);   SYM(__nv_bfloat16, xl, g_xl);
    SYM(__nv_bfloat16, eWh, g_eWh); SYM(__nv_bfloat16, eWl, g_eWl);
    SYM(__nv_bfloat16, iWh, g_iWh); SYM(__nv_bfloat16, iWl, g_iWl);
    SYM(__nv_bfloat16, oWh, g_oWh); SYM(__nv_bfloat16, oWl, g_oWl);
    SYM(__nv_bfloat16, dWh, g_dWh); SYM(__nv_bfloat16, dWl, g_dWl);
    SYM(__nv_bfloat16, zh, g_zh);   SYM(__nv_bfloat16, zl, g_zl);
    SYM(float, qkvf, g_qkv);
    SYM(__nv_bfloat16, Qh, g_Qh);   SYM(__nv_bfloat16, Ql, g_Ql);
    SYM(__nv_bfloat16, Kh, g_Kh);   SYM(__nv_bfloat16, Kl, g_Kl);
    SYM(__nv_bfloat16, Vth, g_Vth); SYM(__nv_bfloat16, Vtl, g_Vtl);
    SYM(float, Sf, g_S);
    SYM(__nv_bfloat16, Ph, g_Ph);   SYM(__nv_bfloat16, Pl, g_Pl);
    SYM(__nv_bfloat16, Oh, g_Oh);   SYM(__nv_bfloat16, Ol, g_Ol);
    SYM(__nv_bfloat16, zrh, g_zrh); SYM(__nv_bfloat16, zrl, g_zrl);
#undef SYM

    // input / weight conversions
    split_plain<<<12288, 256>>>((const float4*)x, xh, xl, 3145728);
    transpose_split<<<dim3(32, 96), dim3(32, 8)>>>(encW, 3072, 1024, eWh, eWl);
    split_plain<<<3072, 256>>>((const float4*)ipW, iWh, iWl, 786432);
    split_plain<<<1024, 256>>>((const float4*)oW, oWh, oWl, 262144);
    transpose_split<<<dim3(96, 32), dim3(32, 8)>>>(decW, 1024, 3072, dWh, dWl);

    // enc: z = X @ encW  (bf16 out)
    gemm_mma3<<<dim3(8, 32, 1), 256, GEMM_SMEM>>>(
        xh, xl, eWh, eWl, nullptr, zh, zl, encb,
        3072, 3072, 3072, 1024, 0, 0, 0, 0, 0, 0, 1);

    // qkv = z @ ipW^T + b (fp32 out)
    gemm_mma3<<<dim3(24, 32, 1), 256, GEMM_SMEM>>>(
        zh, zl, iWh, iWl, qkvf, nullptr, nullptr, ipb,
        1024, 1024, 1024, 3072, 0, 0, 0, 0, 0, 0, 1);

    qkv_split<<<dim3(512, 64), 128>>>(qkvf, Qh, Ql, Kh, Kl);
    vt_split<<<dim3(4, 16, 64), dim3(32, 8)>>>(qkvf, Vth, Vtl);

    // scores: S = Q @ K^T (64 batches of 512x512x128)
    gemm_mma3<<<dim3(4, 4, 64), 256, GEMM_SMEM>>>(
        Qh, Ql, Kh, Kl, Sf, nullptr, nullptr, nullptr,
        128, 128, 128, 512, 65536, 0, 65536, 0, 262144, 0, 1);

    softmax_split<<<32768, 256>>>(Sf, Ph, Pl);

    // O = P @ V (64 batches of 512x128x512, strided bf16 out into 4096x1024)
    gemm_mma3<<<dim3(1, 4, 64), 256, GEMM_SMEM>>>(
        Ph, Pl, Vth, Vtl, nullptr, Oh, Ol, nullptr,
        512, 512, 512, 8192, 2097152, 262144, 524288, 65536, 1024, 128, 8);

    // zrec = O @ oW^T + b (bf16 out)
    gemm_mma3<<<dim3(8, 32, 1), 256, GEMM_SMEM>>>(
        Oh, Ol, oWh, oWl, nullptr, zrh, zrl, ob,
        1024, 1024, 1024, 1024, 0, 0, 0, 0, 0, 0, 1);

    // xrec = zrec @ decW + b (fp32 -> d_out)
    gemm_mma3<<<dim3(24, 32, 1), 256, GEMM_SMEM>>>(
        zrh, zrl, dWh, dWl, rec, nullptr, nullptr, decb,
        1024, 1024, 1024, 3072, 0, 0, 0, 0, 0, 0, 1);

    pred_copy<<<6144, 256>>>(rec, pred);
}